// round 5
// baseline (speedup 1.0000x reference)
#include <cuda_runtime.h>

#define DM   1024
#define HEADS 16
#define DH    64
#define POS  2048
#define BATCH 2
#define TOK  (BATCH*POS)   // 4096

// ---------------- scratch (device globals: allocation-free) ----------------
__device__ float g_Q[TOK*DM];
__device__ float g_K[TOK*DM];
__device__ float g_V[TOK*DM];
__device__ float g_A[TOK*DM];

// ---------------- packed f32x2 helpers (Blackwell FFMA2 path) ----------------
__device__ __forceinline__ void ffma2(unsigned long long &c, unsigned long long a, unsigned long long b) {
    asm("fma.rn.f32x2 %0, %1, %2, %0;" : "+l"(c) : "l"(a), "l"(b));
}
__device__ __forceinline__ void fmul2(unsigned long long &c, unsigned long long a) {
    asm("mul.rn.f32x2 %0, %0, %1;" : "+l"(c) : "l"(a));
}
__device__ __forceinline__ unsigned long long pk2(float lo, float hi) {
    unsigned long long r; asm("mov.b64 %0, {%1,%2};" : "=l"(r) : "f"(lo), "f"(hi)); return r;
}
__device__ __forceinline__ float2 upk2(unsigned long long v) {
    float2 r; asm("mov.b64 {%0,%1}, %2;" : "=f"(r.x), "=f"(r.y) : "l"(v)); return r;
}
__device__ __forceinline__ unsigned long long bc2(float a) { return pk2(a, a); }

// ---------------- generic 128x128x16 GEMM ----------------
// MODE 0: QKV projection. A = X [TOK x DM]. B element (k,n): W[h=n>>6][k][d=n&63].
//         blockIdx.z selects (Wq,g_Q)/(Wk,g_K)/(Wv,g_V).
// MODE 1: out projection. B element (k,n) = W[k*DM + n].
template<int MODE>
__global__ __launch_bounds__(256, 2)
void gemm_kernel(const float* __restrict__ A,
                 const float* __restrict__ W0, const float* __restrict__ W1, const float* __restrict__ W2,
                 float* __restrict__ O0, float* __restrict__ O1, float* __restrict__ O2,
                 int K)
{
    const int BM = 128, BN = 128, BK = 16;
    __shared__ float As[BK][BM + 4];  // k-major, transposed A tile
    __shared__ float Bs[BK][BN + 4];

    int tid = threadIdx.x;
    int m0 = blockIdx.y * BM;
    int n0 = blockIdx.x * BN;

    const float* W;
    float* O;
    if (MODE == 0) {
        int z = blockIdx.z;
        W = (z == 0) ? W0 : (z == 1) ? W1 : W2;
        O = (z == 0) ? O0 : (z == 1) ? O1 : O2;
    } else {
        W = W0; O = O0;
    }

    const int N = DM;
    int tr = tid >> 4, tc = tid & 15;
    int row0 = tr * 8, col0 = tc * 8;

    unsigned long long c2[8][4];
#pragma unroll
    for (int r = 0; r < 8; r++)
#pragma unroll
        for (int p = 0; p < 4; p++) c2[r][p] = 0ull;

    for (int k0 = 0; k0 < K; k0 += BK) {
        // load A tile (128 x 16), store transposed into As[k][m]
#pragma unroll
        for (int i = 0; i < 2; i++) {
            int id = tid * 2 + i;
            int ar = id >> 2;              // 4 float4 per row of 16
            int ac = (id & 3) * 4;
            float4 v = *(const float4*)(A + (size_t)(m0 + ar) * K + k0 + ac);
            As[ac + 0][ar] = v.x; As[ac + 1][ar] = v.y;
            As[ac + 2][ar] = v.z; As[ac + 3][ar] = v.w;
        }
        // load B tile (16 x 128)
#pragma unroll
        for (int i = 0; i < 2; i++) {
            int id = tid * 2 + i;
            int br = id >> 5;              // 32 float4 per row of 128
            int bc = (id & 31) * 4;
            const float* src;
            if (MODE == 0) {
                int n = n0 + bc;           // bc%4==0, never crosses a 64-wide head boundary
                src = W + (size_t)(n >> 6) * (DM * DH) + (size_t)(k0 + br) * DH + (n & 63);
            } else {
                src = W + (size_t)(k0 + br) * N + n0 + bc;
            }
            float4 v = *(const float4*)src;
            *(float4*)&Bs[br][bc] = v;
        }
        __syncthreads();

#pragma unroll
        for (int kk = 0; kk < BK; kk++) {
            float4 a0 = *(float4*)&As[kk][row0];
            float4 a1 = *(float4*)&As[kk][row0 + 4];
            float4 b0 = *(float4*)&Bs[kk][col0];
            float4 b1 = *(float4*)&Bs[kk][col0 + 4];
            unsigned long long bp[4] = { pk2(b0.x, b0.y), pk2(b0.z, b0.w),
                                         pk2(b1.x, b1.y), pk2(b1.z, b1.w) };
            float av[8] = { a0.x, a0.y, a0.z, a0.w, a1.x, a1.y, a1.z, a1.w };
#pragma unroll
            for (int r = 0; r < 8; r++) {
                unsigned long long ap = bc2(av[r]);
#pragma unroll
                for (int p = 0; p < 4; p++) ffma2(c2[r][p], ap, bp[p]);
            }
        }
        __syncthreads();
    }

#pragma unroll
    for (int r = 0; r < 8; r++) {
#pragma unroll
        for (int p = 0; p < 4; p++) {
            float2 v = upk2(c2[r][p]);
            *(float2*)(O + (size_t)(m0 + row0 + r) * N + n0 + col0 + p * 2) = v;
        }
    }
}

// ---------------- flash-attention (causal), 64q x 64k tiles, d=64 ----------------
// Reads g_Q/g_K/g_V ([tok][h*64+d]), writes g_A in [b,p,h,d] concat layout.
#define ATTN_SMEM_FLOATS (4*64*68 + 256 + 3*64)
#define ATTN_SMEM_BYTES  (ATTN_SMEM_FLOATS * 4)

__global__ __launch_bounds__(256, 2)
void attn_kernel()
{
    extern __shared__ float sm[];
    float* Qs   = sm;              // [64][68]  d-major:  Qs[d*68 + i]
    float* Ks   = Qs + 64 * 68;    // [64][68]  d-major:  Ks[d*68 + j]
    float* Vs   = Ks + 64 * 68;    // [64][68]  tok-major: Vs[j*68 + d]
    float* Ps   = Vs + 64 * 68;    // [64][68]  TRANSPOSED scores: Ps[j*68 + r]
    float* red  = Ps + 64 * 68;    // [64*4]
    float* mrow = red + 256;       // [64]
    float* arow = mrow + 64;       // [64]
    float* lrow = arow + 64;       // [64]

    int tid = threadIdx.x;
    int qt = blockIdx.x, h = blockIdx.y, b = blockIdx.z;
    int q0 = qt * 64;

    // load Q tile transposed
#pragma unroll
    for (int i = 0; i < 4; i++) {
        int id = tid + 256 * i;
        int tok = id >> 4;
        int d4 = (id & 15) * 4;
        float4 v = *(const float4*)(g_Q + (size_t)(b * POS + q0 + tok) * DM + h * DH + d4);
        Qs[(d4 + 0) * 68 + tok] = v.x; Qs[(d4 + 1) * 68 + tok] = v.y;
        Qs[(d4 + 2) * 68 + tok] = v.z; Qs[(d4 + 3) * 68 + tok] = v.w;
    }
    if (tid < 64) { mrow[tid] = -1e30f; lrow[tid] = 0.0f; }

    unsigned long long o2[4][2];
#pragma unroll
    for (int x = 0; x < 4; x++) { o2[x][0] = 0ull; o2[x][1] = 0ull; }

    int ti = tid & 15, tj = tid >> 4;
    int r0 = ti * 4;          // query rows owned (S and O)
    int j0 = tj * 4;          // key cols owned (S)
    int c0 = tj * 4;          // d cols owned (O)
    __syncthreads();

    for (int kt = 0; kt <= qt; kt++) {
        int k0 = kt * 64;
        // load K (transposed) and V (row-major) tiles
#pragma unroll
        for (int i = 0; i < 4; i++) {
            int id = tid + 256 * i;
            int tok = id >> 4;
            int d4 = (id & 15) * 4;
            float4 kv = *(const float4*)(g_K + (size_t)(b * POS + k0 + tok) * DM + h * DH + d4);
            Ks[(d4 + 0) * 68 + tok] = kv.x; Ks[(d4 + 1) * 68 + tok] = kv.y;
            Ks[(d4 + 2) * 68 + tok] = kv.z; Ks[(d4 + 3) * 68 + tok] = kv.w;
            float4 vv = *(const float4*)(g_V + (size_t)(b * POS + k0 + tok) * DM + h * DH + d4);
            *(float4*)&Vs[tok * 68 + d4] = vv;
        }
        __syncthreads();

        // S = Q K^T over d=64
        unsigned long long s2[4][2];
#pragma unroll
        for (int x = 0; x < 4; x++) { s2[x][0] = 0ull; s2[x][1] = 0ull; }
#pragma unroll 16
        for (int kk = 0; kk < 64; kk++) {
            float4 qv = *(float4*)&Qs[kk * 68 + r0];
            float4 kv = *(float4*)&Ks[kk * 68 + j0];
            unsigned long long kp0 = pk2(kv.x, kv.y), kp1 = pk2(kv.z, kv.w);
            float qa[4] = { qv.x, qv.y, qv.z, qv.w };
#pragma unroll
            for (int x = 0; x < 4; x++) {
                unsigned long long ap = bc2(qa[x]);
                ffma2(s2[x][0], ap, kp0);
                ffma2(s2[x][1], ap, kp1);
            }
        }
        // scale + causal mask, keep local copy, write transposed
        float sl[4][4];
#pragma unroll
        for (int x = 0; x < 4; x++) {
            float2 v0 = upk2(s2[x][0]), v1 = upk2(s2[x][1]);
            sl[x][0] = v0.x * 0.125f; sl[x][1] = v0.y * 0.125f;
            sl[x][2] = v1.x * 0.125f; sl[x][3] = v1.y * 0.125f;
        }
        if (kt == qt) {
#pragma unroll
            for (int x = 0; x < 4; x++)
#pragma unroll
                for (int y = 0; y < 4; y++)
                    if (j0 + y > r0 + x) sl[x][y] = -1e30f;
        }
#pragma unroll
        for (int x = 0; x < 4; x++)
#pragma unroll
            for (int y = 0; y < 4; y++)
                Ps[(j0 + y) * 68 + (r0 + x)] = sl[x][y];
        __syncthreads();

        // row max (4 partials per row)
        {
            int r = tid >> 2, part = tid & 3;
            float pm = -1e30f;
#pragma unroll
            for (int jj = 0; jj < 16; jj++)
                pm = fmaxf(pm, Ps[(part * 16 + jj) * 68 + r]);
            red[r * 4 + part] = pm;
        }
        __syncthreads();
        if (tid < 64) {
            int r = tid;
            float mt = fmaxf(fmaxf(red[r*4], red[r*4+1]), fmaxf(red[r*4+2], red[r*4+3]));
            float mo = mrow[r];
            float mn = fmaxf(mo, mt);
            arow[r] = __expf(mo - mn);
            mrow[r] = mn;
        }
        __syncthreads();

        // exponentiate (local), write back; rescale running O by alpha
#pragma unroll
        for (int x = 0; x < 4; x++) {
            float mr = mrow[r0 + x];
#pragma unroll
            for (int y = 0; y < 4; y++) {
                float p = __expf(sl[x][y] - mr);
                Ps[(j0 + y) * 68 + (r0 + x)] = p;
            }
        }
#pragma unroll
        for (int x = 0; x < 4; x++) {
            unsigned long long aa = bc2(arow[r0 + x]);
            fmul2(o2[x][0], aa);
            fmul2(o2[x][1], aa);
        }
        __syncthreads();

        // row sum (4 partials per row)
        {
            int r = tid >> 2, part = tid & 3;
            float ps = 0.0f;
#pragma unroll
            for (int jj = 0; jj < 16; jj++)
                ps += Ps[(part * 16 + jj) * 68 + r];
            red[r * 4 + part] = ps;
        }
        __syncthreads();
        if (tid < 64) {
            int r = tid;
            lrow[r] = lrow[r] * arow[r] + (red[r*4] + red[r*4+1] + red[r*4+2] + red[r*4+3]);
        }

        // O += P * V
#pragma unroll 16
        for (int j = 0; j < 64; j++) {
            float4 pv = *(float4*)&Ps[j * 68 + r0];
            float4 vv = *(float4*)&Vs[j * 68 + c0];
            unsigned long long vp0 = pk2(vv.x, vv.y), vp1 = pk2(vv.z, vv.w);
            float pa[4] = { pv.x, pv.y, pv.z, pv.w };
#pragma unroll
            for (int x = 0; x < 4; x++) {
                unsigned long long pp = bc2(pa[x]);
                ffma2(o2[x][0], pp, vp0);
                ffma2(o2[x][1], pp, vp1);
            }
        }
        __syncthreads();
    }

    // finalize: O / l, write concat layout [b,p,h,d]
#pragma unroll
    for (int x = 0; x < 4; x++) {
        float inv = 1.0f / lrow[r0 + x];
        float2 v0 = upk2(o2[x][0]);
        float2 v1 = upk2(o2[x][1]);
        v0.x *= inv; v0.y *= inv; v1.x *= inv; v1.y *= inv;
        float* dst = g_A + (size_t)(b * POS + q0 + r0 + x) * DM + h * DH + c0;
        *(float2*)(dst)     = v0;
        *(float2*)(dst + 2) = v1;
    }
}

// ---------------- launch ----------------
extern "C" void kernel_launch(void* const* d_in, const int* in_sizes, int n_in,
                              void* d_out, int out_size)
{
    (void)in_sizes; (void)n_in; (void)out_size;
    const float* X  = (const float*)d_in[0];
    const float* Wq = (const float*)d_in[1];
    const float* Wk = (const float*)d_in[2];
    const float* Wv = (const float*)d_in[3];
    const float* Wo = (const float*)d_in[4];
    float* out = (float*)d_out;

    float *Qp, *Kp, *Vp, *Ap;
    cudaGetSymbolAddress((void**)&Qp, g_Q);
    cudaGetSymbolAddress((void**)&Kp, g_K);
    cudaGetSymbolAddress((void**)&Vp, g_V);
    cudaGetSymbolAddress((void**)&Ap, g_A);

    cudaFuncSetAttribute(attn_kernel, cudaFuncAttributeMaxDynamicSharedMemorySize, ATTN_SMEM_BYTES);

    // 1) fused QKV projection: X[4096x1024] x W[1024x1024] (head-blocked) -> Q,K,V
    dim3 g1(DM / 128, TOK / 128, 3);
    gemm_kernel<0><<<g1, 256>>>(X, Wq, Wk, Wv, Qp, Kp, Vp, DM);

    // 2) causal flash attention per (q-tile, head, batch)
    dim3 g2(POS / 64, HEADS, BATCH);
    attn_kernel<<<g2, 256, ATTN_SMEM_BYTES>>>();

    // 3) out projection: attn_concat[4096x1024] x Wo[1024x1024] -> out
    dim3 g3(DM / 128, TOK / 128, 1);
    gemm_kernel<1><<<g3, 256>>>(Ap, Wo, nullptr, nullptr, out, nullptr, nullptr, DM);
}

// round 8
// speedup vs baseline: 1.4590x; 1.4590x over previous
#include <cuda_runtime.h>
#include <cuda_bf16.h>

#define DM   1024
#define HEADS 16
#define DH    64
#define POS  2048
#define BATCH 2
#define TOK  (BATCH*POS)   // 4096

// ---------------- scratch (device globals: allocation-free) ----------------
__device__ float g_Q[TOK*DM];
__device__ float g_K[TOK*DM];
__device__ float g_V[TOK*DM];
__device__ float g_A[TOK*DM];

__device__ __nv_bfloat16 g_Xh[TOK*DM], g_Xl[TOK*DM];
__device__ __nv_bfloat16 g_Ah[TOK*DM], g_Al[TOK*DM];
__device__ __nv_bfloat16 g_Wqh[DM*DM], g_Wql[DM*DM];
__device__ __nv_bfloat16 g_Wkh[DM*DM], g_Wkl[DM*DM];
__device__ __nv_bfloat16 g_Wvh[DM*DM], g_Wvl[DM*DM];
__device__ __nv_bfloat16 g_Woh[DM*DM], g_Wol[DM*DM];

// ---------------- helpers ----------------
__device__ __forceinline__ unsigned smem_u32(const void* p) {
    unsigned r;
    asm("{ .reg .u64 t; cvta.to.shared.u64 t, %1; cvt.u32.u64 %0, t; }" : "=r"(r) : "l"(p));
    return r;
}
__device__ __forceinline__ void cp16(unsigned s, const void* g) {
    asm volatile("cp.async.cg.shared.global [%0], [%1], 16;" :: "r"(s), "l"(g) : "memory");
}
#define CP_ASYNC_COMMIT() asm volatile("cp.async.commit_group;" ::: "memory")
#define CP_ASYNC_WAIT1()  asm volatile("cp.async.wait_group 1;" ::: "memory")
#define CP_ASYNC_WAIT0()  asm volatile("cp.async.wait_group 0;" ::: "memory")

__device__ __forceinline__ void ldsm4(unsigned* r, unsigned a) {
    asm volatile("ldmatrix.sync.aligned.m8n8.x4.shared.b16 {%0,%1,%2,%3}, [%4];"
        : "=r"(r[0]), "=r"(r[1]), "=r"(r[2]), "=r"(r[3]) : "r"(a));
}
__device__ __forceinline__ void ldsm2(unsigned* r, unsigned a) {
    asm volatile("ldmatrix.sync.aligned.m8n8.x2.shared.b16 {%0,%1}, [%2];"
        : "=r"(r[0]), "=r"(r[1]) : "r"(a));
}
__device__ __forceinline__ void mma_bf16(float* d, const unsigned* a, const unsigned* b) {
    asm volatile("mma.sync.aligned.m16n8k16.row.col.f32.bf16.bf16.f32 "
        "{%0,%1,%2,%3}, {%4,%5,%6,%7}, {%8,%9}, {%0,%1,%2,%3};"
        : "+f"(d[0]), "+f"(d[1]), "+f"(d[2]), "+f"(d[3])
        : "r"(a[0]), "r"(a[1]), "r"(a[2]), "r"(a[3]), "r"(b[0]), "r"(b[1]));
}

// ---------------- fp32 -> bf16 hi/lo split kernels ----------------
__global__ void split_f32(const float4* __restrict__ src,
                          __nv_bfloat162* __restrict__ h, __nv_bfloat162* __restrict__ l, int n4)
{
    int i = blockIdx.x * blockDim.x + threadIdx.x;
    if (i >= n4) return;
    float4 v = src[i];
    __nv_bfloat16 hx = __float2bfloat16(v.x);
    __nv_bfloat16 hy = __float2bfloat16(v.y);
    __nv_bfloat16 hz = __float2bfloat16(v.z);
    __nv_bfloat16 hw = __float2bfloat16(v.w);
    h[i*2+0] = __halves2bfloat162(hx, hy);
    h[i*2+1] = __halves2bfloat162(hz, hw);
    l[i*2+0] = __halves2bfloat162(__float2bfloat16(v.x - __bfloat162float(hx)),
                                  __float2bfloat16(v.y - __bfloat162float(hy)));
    l[i*2+1] = __halves2bfloat162(__float2bfloat16(v.z - __bfloat162float(hz)),
                                  __float2bfloat16(v.w - __bfloat162float(hw)));
}

// Weight transpose+split: out[n][k] bf16 hi/lo.
// QKV=1: src element (k,n) = W[n>>6][k][n&63].  QKV=0: src (k,n) = W[k*DM+n].
template<int QKV>
__global__ void split_w(const float* __restrict__ W,
                        __nv_bfloat16* __restrict__ h, __nv_bfloat16* __restrict__ l)
{
    int idx = blockIdx.x * blockDim.x + threadIdx.x;   // over DM*DM
    int n = idx >> 10, k = idx & 1023;
    float x = QKV ? W[(size_t)(n >> 6) * (DM * DH) + (size_t)k * DH + (n & 63)]
                  : W[(size_t)k * DM + n];
    __nv_bfloat16 hi = __float2bfloat16(x);
    h[idx] = hi;
    l[idx] = __float2bfloat16(x - __bfloat162float(hi));
}

// ---------------- HMMA split-bf16 GEMM: O[4096x1024] = A x B^T ----------------
// A: [4096][1024] bf16 hi/lo.  B: [1024 n][1024 k] bf16 hi/lo.  O fp32.
// CTA tile 128x128, 8 warps (warp tile 64x32), K-chunk 32 bf16 (64B) x 32 chunks,
// double-buffered cp.async. smem per stage: 4 tiles x 128 rows x 80B = 40960 B.
#define TILE_B   10240
#define STAGE_B  40960
#define NCHUNK   32
#define GEMM_SMEM_BYTES (2*STAGE_B)

__global__ __launch_bounds__(256, 1)
void mma_gemm(const __nv_bfloat16* __restrict__ Ah, const __nv_bfloat16* __restrict__ Al,
              const __nv_bfloat16* __restrict__ B0h, const __nv_bfloat16* __restrict__ B0l,
              const __nv_bfloat16* __restrict__ B1h, const __nv_bfloat16* __restrict__ B1l,
              const __nv_bfloat16* __restrict__ B2h, const __nv_bfloat16* __restrict__ B2l,
              float* __restrict__ O0, float* __restrict__ O1, float* __restrict__ O2)
{
    extern __shared__ __align__(128) char smem[];
    const unsigned sb = smem_u32(smem);
    int tid = threadIdx.x, lane = tid & 31, wid = tid >> 5;
    int n0 = blockIdx.x * 128, m0 = blockIdx.y * 128;
    int z = blockIdx.z;
    const char* pAh = (const char*)Ah;
    const char* pAl = (const char*)Al;
    const char* pBh = (const char*)((z == 0) ? B0h : (z == 1) ? B1h : B2h);
    const char* pBl = (const char*)((z == 0) ? B0l : (z == 1) ? B1l : B2l);
    float* O = (z == 0) ? O0 : (z == 1) ? O1 : O2;

    int wm = (wid & 1) * 64;       // warp M offset in tile
    int wn = (wid >> 1) * 32;      // warp N offset in tile

    // per-thread load mapping: 8 x 16B cp.async per chunk
    int lrow = tid >> 2;           // 0..63 -> covers rows via 2 sub-batches
    int lcol = (tid & 3) * 16;     // byte col within 64B chunk row

    float acc[4][4][4];
#pragma unroll
    for (int mi = 0; mi < 4; mi++)
#pragma unroll
        for (int ni = 0; ni < 4; ni++)
#pragma unroll
            for (int e = 0; e < 4; e++) acc[mi][ni][e] = 0.0f;

    // ---- chunk loader ----
    auto load_chunk = [&](int c, int st) {
        int k0b = c * 64;   // byte offset into K (32 bf16 = 64B per chunk; 32 chunks = 2048B)
#pragma unroll
        for (int half = 0; half < 2; half++) {
            int row = lrow + half * 64;
            unsigned sa = sb + st * STAGE_B + row * 80 + lcol;
            size_t goffA = ((size_t)(m0 + row) * DM) * 2 + k0b + lcol;
            size_t goffB = ((size_t)(n0 + row) * DM) * 2 + k0b + lcol;
            cp16(sa,              pAh + goffA);
            cp16(sa + TILE_B,     pAl + goffA);
            cp16(sa + 2*TILE_B,   pBh + goffB);
            cp16(sa + 3*TILE_B,   pBl + goffB);
        }
    };

    load_chunk(0, 0);
    CP_ASYNC_COMMIT();

    // fragment address bases (padded stride 80B: row shifts mod 128B all distinct -> conflict-free)
    unsigned a_base = (wm + (lane & 15)) * 80 + ((lane >> 4) << 4);
    unsigned b_base = 2*TILE_B + (wn + (lane & 7)) * 80 + (((lane >> 3) & 1) << 4);

    for (int c = 0; c < NCHUNK; c++) {
        if (c + 1 < NCHUNK) {
            load_chunk(c + 1, (c + 1) & 1);
            CP_ASYNC_COMMIT();
            CP_ASYNC_WAIT1();
        } else {
            CP_ASYNC_WAIT0();
        }
        __syncthreads();

        unsigned stb = sb + (c & 1) * STAGE_B;
#pragma unroll
        for (int ks = 0; ks < 2; ks++) {
            unsigned af[4][4], bh[4][2], bl[4][2];
            unsigned ka = stb + ks * 32;
#pragma unroll
            for (int mi = 0; mi < 4; mi++) ldsm4(af[mi], ka + a_base + mi * (16 * 80));
#pragma unroll
            for (int ni = 0; ni < 4; ni++) {
                ldsm2(bh[ni], ka + b_base + ni * (8 * 80));
                ldsm2(bl[ni], ka + b_base + TILE_B + ni * (8 * 80));
            }
            // term Ah*Bh
#pragma unroll
            for (int mi = 0; mi < 4; mi++)
#pragma unroll
                for (int ni = 0; ni < 4; ni++) mma_bf16(acc[mi][ni], af[mi], bh[ni]);
            // term Ah*Bl
#pragma unroll
            for (int mi = 0; mi < 4; mi++)
#pragma unroll
                for (int ni = 0; ni < 4; ni++) mma_bf16(acc[mi][ni], af[mi], bl[ni]);
            // term Al*Bh (reload A frags as Al)
#pragma unroll
            for (int mi = 0; mi < 4; mi++) ldsm4(af[mi], ka + a_base + TILE_B + mi * (16 * 80));
#pragma unroll
            for (int mi = 0; mi < 4; mi++)
#pragma unroll
                for (int ni = 0; ni < 4; ni++) mma_bf16(acc[mi][ni], af[mi], bh[ni]);
        }
        __syncthreads();
    }

    // ---- epilogue: direct fp32 stores ----
    int g = lane >> 2, t = lane & 3;
#pragma unroll
    for (int mi = 0; mi < 4; mi++) {
#pragma unroll
        for (int ni = 0; ni < 4; ni++) {
            int row = m0 + wm + mi * 16 + g;
            int col = n0 + wn + ni * 8 + t * 2;
            float2 v0 = { acc[mi][ni][0], acc[mi][ni][1] };
            float2 v1 = { acc[mi][ni][2], acc[mi][ni][3] };
            *(float2*)(O + (size_t)row * DM + col)       = v0;
            *(float2*)(O + (size_t)(row + 8) * DM + col) = v1;
        }
    }
}

// ---------------- packed f32x2 helpers (attention kernel) ----------------
__device__ __forceinline__ void ffma2(unsigned long long &c, unsigned long long a, unsigned long long b) {
    asm("fma.rn.f32x2 %0, %1, %2, %0;" : "+l"(c) : "l"(a), "l"(b));
}
__device__ __forceinline__ void fmul2(unsigned long long &c, unsigned long long a) {
    asm("mul.rn.f32x2 %0, %0, %1;" : "+l"(c) : "l"(a));
}
__device__ __forceinline__ unsigned long long pk2(float lo, float hi) {
    unsigned long long r; asm("mov.b64 %0, {%1,%2};" : "=l"(r) : "f"(lo), "f"(hi)); return r;
}
__device__ __forceinline__ float2 upk2(unsigned long long v) {
    float2 r; asm("mov.b64 {%0,%1}, %2;" : "=f"(r.x), "=f"(r.y) : "l"(v)); return r;
}
__device__ __forceinline__ unsigned long long bc2(float a) { return pk2(a, a); }

// ---------------- flash-attention (causal), 64q x 64k tiles, d=64 ----------------
#define ATTN_SMEM_FLOATS (4*64*68 + 256 + 3*64)
#define ATTN_SMEM_BYTES  (ATTN_SMEM_FLOATS * 4)

__global__ __launch_bounds__(256, 2)
void attn_kernel()
{
    extern __shared__ float sm[];
    float* Qs   = sm;              // [64][68]  d-major:  Qs[d*68 + i]
    float* Ks   = Qs + 64 * 68;    // [64][68]  d-major:  Ks[d*68 + j]
    float* Vs   = Ks + 64 * 68;    // [64][68]  tok-major: Vs[j*68 + d]
    float* Ps   = Vs + 64 * 68;    // [64][68]  TRANSPOSED scores: Ps[j*68 + r]
    float* red  = Ps + 64 * 68;    // [64*4]
    float* mrow = red + 256;       // [64]
    float* arow = mrow + 64;       // [64]
    float* lrow = arow + 64;       // [64]

    int tid = threadIdx.x;
    int qt = blockIdx.x, h = blockIdx.y, b = blockIdx.z;
    int q0 = qt * 64;

#pragma unroll
    for (int i = 0; i < 4; i++) {
        int id = tid + 256 * i;
        int tok = id >> 4;
        int d4 = (id & 15) * 4;
        float4 v = *(const float4*)(g_Q + (size_t)(b * POS + q0 + tok) * DM + h * DH + d4);
        Qs[(d4 + 0) * 68 + tok] = v.x; Qs[(d4 + 1) * 68 + tok] = v.y;
        Qs[(d4 + 2) * 68 + tok] = v.z; Qs[(d4 + 3) * 68 + tok] = v.w;
    }
    if (tid < 64) { mrow[tid] = -1e30f; lrow[tid] = 0.0f; }

    unsigned long long o2[4][2];
#pragma unroll
    for (int x = 0; x < 4; x++) { o2[x][0] = 0ull; o2[x][1] = 0ull; }

    int ti = tid & 15, tj = tid >> 4;
    int r0 = ti * 4;
    int j0 = tj * 4;
    int c0 = tj * 4;
    __syncthreads();

    for (int kt = 0; kt <= qt; kt++) {
        int k0 = kt * 64;
#pragma unroll
        for (int i = 0; i < 4; i++) {
            int id = tid + 256 * i;
            int tok = id >> 4;
            int d4 = (id & 15) * 4;
            float4 kv = *(const float4*)(g_K + (size_t)(b * POS + k0 + tok) * DM + h * DH + d4);
            Ks[(d4 + 0) * 68 + tok] = kv.x; Ks[(d4 + 1) * 68 + tok] = kv.y;
            Ks[(d4 + 2) * 68 + tok] = kv.z; Ks[(d4 + 3) * 68 + tok] = kv.w;
            float4 vv = *(const float4*)(g_V + (size_t)(b * POS + k0 + tok) * DM + h * DH + d4);
            *(float4*)&Vs[tok * 68 + d4] = vv;
        }
        __syncthreads();

        unsigned long long s2[4][2];
#pragma unroll
        for (int x = 0; x < 4; x++) { s2[x][0] = 0ull; s2[x][1] = 0ull; }
#pragma unroll 16
        for (int kk = 0; kk < 64; kk++) {
            float4 qv = *(float4*)&Qs[kk * 68 + r0];
            float4 kv = *(float4*)&Ks[kk * 68 + j0];
            unsigned long long kp0 = pk2(kv.x, kv.y), kp1 = pk2(kv.z, kv.w);
            float qa[4] = { qv.x, qv.y, qv.z, qv.w };
#pragma unroll
            for (int x = 0; x < 4; x++) {
                unsigned long long ap = bc2(qa[x]);
                ffma2(s2[x][0], ap, kp0);
                ffma2(s2[x][1], ap, kp1);
            }
        }
        float sl[4][4];
#pragma unroll
        for (int x = 0; x < 4; x++) {
            float2 v0 = upk2(s2[x][0]), v1 = upk2(s2[x][1]);
            sl[x][0] = v0.x * 0.125f; sl[x][1] = v0.y * 0.125f;
            sl[x][2] = v1.x * 0.125f; sl[x][3] = v1.y * 0.125f;
        }
        if (kt == qt) {
#pragma unroll
            for (int x = 0; x < 4; x++)
#pragma unroll
                for (int y = 0; y < 4; y++)
                    if (j0 + y > r0 + x) sl[x][y] = -1e30f;
        }
#pragma unroll
        for (int x = 0; x < 4; x++)
#pragma unroll
            for (int y = 0; y < 4; y++)
                Ps[(j0 + y) * 68 + (r0 + x)] = sl[x][y];
        __syncthreads();

        {
            int r = tid >> 2, part = tid & 3;
            float pm = -1e30f;
#pragma unroll
            for (int jj = 0; jj < 16; jj++)
                pm = fmaxf(pm, Ps[(part * 16 + jj) * 68 + r]);
            red[r * 4 + part] = pm;
        }
        __syncthreads();
        if (tid < 64) {
            int r = tid;
            float mt = fmaxf(fmaxf(red[r*4], red[r*4+1]), fmaxf(red[r*4+2], red[r*4+3]));
            float mo = mrow[r];
            float mn = fmaxf(mo, mt);
            arow[r] = __expf(mo - mn);
            mrow[r] = mn;
        }
        __syncthreads();

#pragma unroll
        for (int x = 0; x < 4; x++) {
            float mr = mrow[r0 + x];
#pragma unroll
            for (int y = 0; y < 4; y++) {
                float p = __expf(sl[x][y] - mr);
                Ps[(j0 + y) * 68 + (r0 + x)] = p;
            }
        }
#pragma unroll
        for (int x = 0; x < 4; x++) {
            unsigned long long aa = bc2(arow[r0 + x]);
            fmul2(o2[x][0], aa);
            fmul2(o2[x][1], aa);
        }
        __syncthreads();

        {
            int r = tid >> 2, part = tid & 3;
            float ps = 0.0f;
#pragma unroll
            for (int jj = 0; jj < 16; jj++)
                ps += Ps[(part * 16 + jj) * 68 + r];
            red[r * 4 + part] = ps;
        }
        __syncthreads();
        if (tid < 64) {
            int r = tid;
            lrow[r] = lrow[r] * arow[r] + (red[r*4] + red[r*4+1] + red[r*4+2] + red[r*4+3]);
        }

#pragma unroll 16
        for (int j = 0; j < 64; j++) {
            float4 pv = *(float4*)&Ps[j * 68 + r0];
            float4 vv = *(float4*)&Vs[j * 68 + c0];
            unsigned long long vp0 = pk2(vv.x, vv.y), vp1 = pk2(vv.z, vv.w);
            float pa[4] = { pv.x, pv.y, pv.z, pv.w };
#pragma unroll
            for (int x = 0; x < 4; x++) {
                unsigned long long pp = bc2(pa[x]);
                ffma2(o2[x][0], pp, vp0);
                ffma2(o2[x][1], pp, vp1);
            }
        }
        __syncthreads();
    }

#pragma unroll
    for (int x = 0; x < 4; x++) {
        float inv = 1.0f / lrow[r0 + x];
        float2 v0 = upk2(o2[x][0]);
        float2 v1 = upk2(o2[x][1]);
        v0.x *= inv; v0.y *= inv; v1.x *= inv; v1.y *= inv;
        float* dst = g_A + (size_t)(b * POS + q0 + r0 + x) * DM + h * DH + c0;
        *(float2*)(dst)     = v0;
        *(float2*)(dst + 2) = v1;
    }
}

// ---------------- launch ----------------
extern "C" void kernel_launch(void* const* d_in, const int* in_sizes, int n_in,
                              void* d_out, int out_size)
{
    (void)in_sizes; (void)n_in; (void)out_size;
    const float* X  = (const float*)d_in[0];
    const float* Wq = (const float*)d_in[1];
    const float* Wk = (const float*)d_in[2];
    const float* Wv = (const float*)d_in[3];
    const float* Wo = (const float*)d_in[4];
    float* out = (float*)d_out;

    float *Qp, *Kp, *Vp, *Ap;
    cudaGetSymbolAddress((void**)&Qp, g_Q);
    cudaGetSymbolAddress((void**)&Kp, g_K);
    cudaGetSymbolAddress((void**)&Vp, g_V);
    cudaGetSymbolAddress((void**)&Ap, g_A);

    __nv_bfloat16 *Xh, *Xl, *Aah, *Aal;
    __nv_bfloat16 *Wqh, *Wql, *Wkh, *Wkl, *Wvh, *Wvl, *Woh, *Wol;
    cudaGetSymbolAddress((void**)&Xh,  g_Xh);  cudaGetSymbolAddress((void**)&Xl,  g_Xl);
    cudaGetSymbolAddress((void**)&Aah, g_Ah);  cudaGetSymbolAddress((void**)&Aal, g_Al);
    cudaGetSymbolAddress((void**)&Wqh, g_Wqh); cudaGetSymbolAddress((void**)&Wql, g_Wql);
    cudaGetSymbolAddress((void**)&Wkh, g_Wkh); cudaGetSymbolAddress((void**)&Wkl, g_Wkl);
    cudaGetSymbolAddress((void**)&Wvh, g_Wvh); cudaGetSymbolAddress((void**)&Wvl, g_Wvl);
    cudaGetSymbolAddress((void**)&Woh, g_Woh); cudaGetSymbolAddress((void**)&Wol, g_Wol);

    cudaFuncSetAttribute(attn_kernel, cudaFuncAttributeMaxDynamicSharedMemorySize, ATTN_SMEM_BYTES);
    cudaFuncSetAttribute(mma_gemm, cudaFuncAttributeMaxDynamicSharedMemorySize, GEMM_SMEM_BYTES);

    // 0) precision splits
    int n4 = TOK * DM / 4;
    split_f32<<<(n4 + 255) / 256, 256>>>((const float4*)X, (__nv_bfloat162*)Xh, (__nv_bfloat162*)Xl, n4);
    int nw = DM * DM;
    split_w<1><<<nw / 256, 256>>>(Wq, Wqh, Wql);
    split_w<1><<<nw / 256, 256>>>(Wk, Wkh, Wkl);
    split_w<1><<<nw / 256, 256>>>(Wv, Wvh, Wvl);
    split_w<0><<<nw / 256, 256>>>(Wo, Woh, Wol);

    // 1) fused QKV projection via HMMA (split-bf16, 3 terms)
    dim3 g1(DM / 128, TOK / 128, 3);
    mma_gemm<<<g1, 256, GEMM_SMEM_BYTES>>>(Xh, Xl, Wqh, Wql, Wkh, Wkl, Wvh, Wvl, Qp, Kp, Vp);

    // 2) causal flash attention
    dim3 g2(POS / 64, HEADS, BATCH);
    attn_kernel<<<g2, 256, ATTN_SMEM_BYTES>>>();

    // 3) split attention output, then out-projection via HMMA
    split_f32<<<(n4 + 255) / 256, 256>>>((const float4*)Ap, (__nv_bfloat162*)Aah, (__nv_bfloat162*)Aal, n4);
    dim3 g3(DM / 128, TOK / 128, 1);
    mma_gemm<<<g3, 256, GEMM_SMEM_BYTES>>>(Aah, Aal, Woh, Wol, nullptr, nullptr, nullptr, nullptr,
                                           out, nullptr, nullptr);
}

// round 9
// speedup vs baseline: 2.8410x; 1.9472x over previous
#include <cuda_runtime.h>
#include <cuda_bf16.h>

#define DM   1024
#define HEADS 16
#define DH    64
#define POS  2048
#define BATCH 2
#define TOK  (BATCH*POS)   // 4096

// ---------------- scratch (device globals: allocation-free) ----------------
__device__ __nv_bfloat16 g_Xh[TOK*DM], g_Xl[TOK*DM];
__device__ __nv_bfloat16 g_Qh[TOK*DM], g_Ql[TOK*DM];
__device__ __nv_bfloat16 g_Kh[TOK*DM], g_Kl[TOK*DM];
__device__ __nv_bfloat16 g_Vh[TOK*DM], g_Vl[TOK*DM];
__device__ __nv_bfloat16 g_Ah[TOK*DM], g_Al[TOK*DM];
__device__ __nv_bfloat16 g_Wqh[DM*DM], g_Wql[DM*DM];
__device__ __nv_bfloat16 g_Wkh[DM*DM], g_Wkl[DM*DM];
__device__ __nv_bfloat16 g_Wvh[DM*DM], g_Wvl[DM*DM];
__device__ __nv_bfloat16 g_Woh[DM*DM], g_Wol[DM*DM];

// ---------------- helpers ----------------
__device__ __forceinline__ unsigned smem_u32(const void* p) {
    unsigned r;
    asm("{ .reg .u64 t; cvta.to.shared.u64 t, %1; cvt.u32.u64 %0, t; }" : "=r"(r) : "l"(p));
    return r;
}
__device__ __forceinline__ void cp16(unsigned s, const void* g) {
    asm volatile("cp.async.cg.shared.global [%0], [%1], 16;" :: "r"(s), "l"(g) : "memory");
}
#define CP_ASYNC_COMMIT() asm volatile("cp.async.commit_group;" ::: "memory")
#define CP_ASYNC_WAIT1()  asm volatile("cp.async.wait_group 1;" ::: "memory")
#define CP_ASYNC_WAIT0()  asm volatile("cp.async.wait_group 0;" ::: "memory")

__device__ __forceinline__ void ldsm4(unsigned* r, unsigned a) {
    asm volatile("ldmatrix.sync.aligned.m8n8.x4.shared.b16 {%0,%1,%2,%3}, [%4];"
        : "=r"(r[0]), "=r"(r[1]), "=r"(r[2]), "=r"(r[3]) : "r"(a));
}
__device__ __forceinline__ void ldsm2(unsigned* r, unsigned a) {
    asm volatile("ldmatrix.sync.aligned.m8n8.x2.shared.b16 {%0,%1}, [%2];"
        : "=r"(r[0]), "=r"(r[1]) : "r"(a));
}
__device__ __forceinline__ void ldsm2t(unsigned* r, unsigned a) {
    asm volatile("ldmatrix.sync.aligned.m8n8.x2.trans.shared.b16 {%0,%1}, [%2];"
        : "=r"(r[0]), "=r"(r[1]) : "r"(a));
}
__device__ __forceinline__ void mma_bf16(float* d, const unsigned* a, const unsigned* b) {
    asm volatile("mma.sync.aligned.m16n8k16.row.col.f32.bf16.bf16.f32 "
        "{%0,%1,%2,%3}, {%4,%5,%6,%7}, {%8,%9}, {%0,%1,%2,%3};"
        : "+f"(d[0]), "+f"(d[1]), "+f"(d[2]), "+f"(d[3])
        : "r"(a[0]), "r"(a[1]), "r"(a[2]), "r"(a[3]), "r"(b[0]), "r"(b[1]));
}
__device__ __forceinline__ unsigned pkbf(float a, float b) {
    __nv_bfloat162 t2 = __halves2bfloat162(__float2bfloat16(a), __float2bfloat16(b));
    return *(unsigned*)&t2;
}

// ---------------- fp32 -> bf16 hi/lo split kernels ----------------
__global__ void split_f32(const float4* __restrict__ src,
                          __nv_bfloat162* __restrict__ h, __nv_bfloat162* __restrict__ l, int n4)
{
    int i = blockIdx.x * blockDim.x + threadIdx.x;
    if (i >= n4) return;
    float4 v = src[i];
    __nv_bfloat16 hx = __float2bfloat16(v.x);
    __nv_bfloat16 hy = __float2bfloat16(v.y);
    __nv_bfloat16 hz = __float2bfloat16(v.z);
    __nv_bfloat16 hw = __float2bfloat16(v.w);
    h[i*2+0] = __halves2bfloat162(hx, hy);
    h[i*2+1] = __halves2bfloat162(hz, hw);
    l[i*2+0] = __halves2bfloat162(__float2bfloat16(v.x - __bfloat162float(hx)),
                                  __float2bfloat16(v.y - __bfloat162float(hy)));
    l[i*2+1] = __halves2bfloat162(__float2bfloat16(v.z - __bfloat162float(hz)),
                                  __float2bfloat16(v.w - __bfloat162float(hw)));
}

// Weight transpose+split: out[n][k] bf16 hi/lo.
template<int QKV>
__global__ void split_w(const float* __restrict__ W,
                        __nv_bfloat16* __restrict__ h, __nv_bfloat16* __restrict__ l)
{
    int idx = blockIdx.x * blockDim.x + threadIdx.x;   // over DM*DM
    int n = idx >> 10, k = idx & 1023;
    float x = QKV ? W[(size_t)(n >> 6) * (DM * DH) + (size_t)k * DH + (n & 63)]
                  : W[(size_t)k * DM + n];
    __nv_bfloat16 hi = __float2bfloat16(x);
    h[idx] = hi;
    l[idx] = __float2bfloat16(x - __bfloat162float(hi));
}

// ---------------- HMMA split-bf16 GEMM: O[4096x1024] = A x B^T ----------------
// MODE 0: epilogue writes bf16 hi/lo (QKV path). MODE 1: fp32 (out-proj).
#define TILE_B   10240
#define STAGE_B  40960
#define NCHUNK   32
#define GEMM_SMEM_BYTES (2*STAGE_B)

template<int MODE>
__global__ __launch_bounds__(256, 1)
void mma_gemm(const __nv_bfloat16* __restrict__ Ah, const __nv_bfloat16* __restrict__ Al,
              const __nv_bfloat16* __restrict__ B0h, const __nv_bfloat16* __restrict__ B0l,
              const __nv_bfloat16* __restrict__ B1h, const __nv_bfloat16* __restrict__ B1l,
              const __nv_bfloat16* __restrict__ B2h, const __nv_bfloat16* __restrict__ B2l,
              float* __restrict__ Of,
              __nv_bfloat16* O0h, __nv_bfloat16* O0l,
              __nv_bfloat16* O1h, __nv_bfloat16* O1l,
              __nv_bfloat16* O2h, __nv_bfloat16* O2l)
{
    extern __shared__ __align__(128) char smem[];
    const unsigned sb = smem_u32(smem);
    int tid = threadIdx.x, lane = tid & 31, wid = tid >> 5;
    int n0 = blockIdx.x * 128, m0 = blockIdx.y * 128;
    int z = blockIdx.z;
    const char* pAh = (const char*)Ah;
    const char* pAl = (const char*)Al;
    const char* pBh = (const char*)((z == 0) ? B0h : (z == 1) ? B1h : B2h);
    const char* pBl = (const char*)((z == 0) ? B0l : (z == 1) ? B1l : B2l);
    __nv_bfloat16* Oh = (z == 0) ? O0h : (z == 1) ? O1h : O2h;
    __nv_bfloat16* Ol = (z == 0) ? O0l : (z == 1) ? O1l : O2l;

    int wm = (wid & 1) * 64;
    int wn = (wid >> 1) * 32;
    int lrow = tid >> 2;
    int lcol = (tid & 3) * 16;

    float acc[4][4][4];
#pragma unroll
    for (int mi = 0; mi < 4; mi++)
#pragma unroll
        for (int ni = 0; ni < 4; ni++)
#pragma unroll
            for (int e = 0; e < 4; e++) acc[mi][ni][e] = 0.0f;

    auto load_chunk = [&](int c, int st) {
        int k0b = c * 64;
#pragma unroll
        for (int half = 0; half < 2; half++) {
            int row = lrow + half * 64;
            unsigned sa = sb + st * STAGE_B + row * 80 + lcol;
            size_t goffA = ((size_t)(m0 + row) * DM) * 2 + k0b + lcol;
            size_t goffB = ((size_t)(n0 + row) * DM) * 2 + k0b + lcol;
            cp16(sa,              pAh + goffA);
            cp16(sa + TILE_B,     pAl + goffA);
            cp16(sa + 2*TILE_B,   pBh + goffB);
            cp16(sa + 3*TILE_B,   pBl + goffB);
        }
    };

    load_chunk(0, 0);
    CP_ASYNC_COMMIT();

    unsigned a_base = (wm + (lane & 15)) * 80 + ((lane >> 4) << 4);
    unsigned b_base = 2*TILE_B + (wn + (lane & 7)) * 80 + (((lane >> 3) & 1) << 4);

    for (int c = 0; c < NCHUNK; c++) {
        if (c + 1 < NCHUNK) {
            load_chunk(c + 1, (c + 1) & 1);
            CP_ASYNC_COMMIT();
            CP_ASYNC_WAIT1();
        } else {
            CP_ASYNC_WAIT0();
        }
        __syncthreads();

        unsigned stb = sb + (c & 1) * STAGE_B;
#pragma unroll
        for (int ks = 0; ks < 2; ks++) {
            unsigned af[4][4], bh[4][2], bl[4][2];
            unsigned ka = stb + ks * 32;
#pragma unroll
            for (int mi = 0; mi < 4; mi++) ldsm4(af[mi], ka + a_base + mi * (16 * 80));
#pragma unroll
            for (int ni = 0; ni < 4; ni++) {
                ldsm2(bh[ni], ka + b_base + ni * (8 * 80));
                ldsm2(bl[ni], ka + b_base + TILE_B + ni * (8 * 80));
            }
#pragma unroll
            for (int mi = 0; mi < 4; mi++)
#pragma unroll
                for (int ni = 0; ni < 4; ni++) mma_bf16(acc[mi][ni], af[mi], bh[ni]);
#pragma unroll
            for (int mi = 0; mi < 4; mi++)
#pragma unroll
                for (int ni = 0; ni < 4; ni++) mma_bf16(acc[mi][ni], af[mi], bl[ni]);
#pragma unroll
            for (int mi = 0; mi < 4; mi++) ldsm4(af[mi], ka + a_base + TILE_B + mi * (16 * 80));
#pragma unroll
            for (int mi = 0; mi < 4; mi++)
#pragma unroll
                for (int ni = 0; ni < 4; ni++) mma_bf16(acc[mi][ni], af[mi], bh[ni]);
        }
        __syncthreads();
    }

    int g = lane >> 2, t = lane & 3;
#pragma unroll
    for (int mi = 0; mi < 4; mi++) {
#pragma unroll
        for (int ni = 0; ni < 4; ni++) {
            int row = m0 + wm + mi * 16 + g;
            int col = n0 + wn + ni * 8 + t * 2;
            if (MODE == 1) {
                float2 v0 = { acc[mi][ni][0], acc[mi][ni][1] };
                float2 v1 = { acc[mi][ni][2], acc[mi][ni][3] };
                *(float2*)(Of + (size_t)row * DM + col)       = v0;
                *(float2*)(Of + (size_t)(row + 8) * DM + col) = v1;
            } else {
#pragma unroll
                for (int rr = 0; rr < 2; rr++) {
                    float vx = acc[mi][ni][rr*2], vy = acc[mi][ni][rr*2+1];
                    __nv_bfloat16 hx = __float2bfloat16(vx);
                    __nv_bfloat16 hy = __float2bfloat16(vy);
                    size_t off = (size_t)(row + rr*8) * DM + col;
                    *(__nv_bfloat162*)(Oh + off) = __halves2bfloat162(hx, hy);
                    *(__nv_bfloat162*)(Ol + off) = __halves2bfloat162(
                        __float2bfloat16(vx - __bfloat162float(hx)),
                        __float2bfloat16(vy - __bfloat162float(hy)));
                }
            }
        }
    }
}

// ---------------- HMMA flash attention (causal) ----------------
// CTA: 128 queries x (b,h). 8 warps, warp = 16 query rows x full 64-key block.
// S = Qh*Kh (1 term).  PV = Ph*Vh + Pl*Vh + Ph*Vl (3 terms).
// K/V tiles double-buffered via cp.async; softmax warp-local (shfl over 4 t-lanes).
#define AQ   128
#define AKB  64
#define QST  144
#define KST  144
#define Q_TILE   (AQ*QST)       // 18432
#define KV_TILE  (AKB*KST)      // 9216
#define KV_STAGE (3*KV_TILE)    // 27648
#define ATTN_SMEM (Q_TILE + 2*KV_STAGE)  // 73728

__global__ __launch_bounds__(256, 1)
void attn_mma()
{
    extern __shared__ __align__(128) char smem[];
    const unsigned sb = smem_u32(smem);
    int tid = threadIdx.x, lane = tid & 31, w = tid >> 5;
    int g = lane >> 2, t = lane & 3;
    int qt = (int)gridDim.x - 1 - (int)blockIdx.x;   // big tiles first
    int h = blockIdx.y, b = blockIdx.z;
    int q0 = qt * AQ;
    const char* pQh = (const char*)g_Qh;
    const char* pKh = (const char*)g_Kh;
    const char* pVh = (const char*)g_Vh;
    const char* pVl = (const char*)g_Vl;

    // stage Q tile (128 rows x 128B)
#pragma unroll
    for (int i = 0; i < 4; i++) {
        int idx = tid + 256 * i;          // 0..1023
        int row = idx >> 3, c16 = idx & 7;
        size_t off = ((size_t)(b * POS + q0 + row) * DM + h * DH) * 2 + c16 * 16;
        cp16(sb + row * QST + c16 * 16, pQh + off);
    }

    auto load_kv = [&](int kb, int st) {
        int k0 = kb * AKB;
        unsigned base = sb + Q_TILE + st * KV_STAGE;
#pragma unroll
        for (int i = 0; i < 2; i++) {
            int idx = tid + 256 * i;      // 0..511
            int row = idx >> 3, c16 = idx & 7;
            size_t off = ((size_t)(b * POS + k0 + row) * DM + h * DH) * 2 + c16 * 16;
            unsigned d = base + row * KST + c16 * 16;
            cp16(d,               pKh + off);
            cp16(d + KV_TILE,     pVh + off);
            cp16(d + 2*KV_TILE,   pVl + off);
        }
    };

    load_kv(0, 0);
    CP_ASYNC_COMMIT();

    int nkb = 2 * (qt + 1);
    int qr0 = q0 + 16 * w + g;            // this thread's first query row
    float m0 = -1e30f, m1 = -1e30f, l0 = 0.0f, l1 = 0.0f;
    float o[8][4];
#pragma unroll
    for (int ni = 0; ni < 8; ni++)
#pragma unroll
        for (int e = 0; e < 4; e++) o[ni][e] = 0.0f;

    unsigned qf[4][4];
    unsigned qa = sb + (16 * w + (lane & 15)) * QST + ((lane >> 4) << 4);

    for (int kb = 0; kb < nkb; kb++) {
        if (kb + 1 < nkb) {
            load_kv(kb + 1, (kb + 1) & 1);
            CP_ASYNC_COMMIT();
            CP_ASYNC_WAIT1();
        } else {
            CP_ASYNC_WAIT0();
        }
        __syncthreads();
        if (kb == 0) {                    // Q is resident after first wait
#pragma unroll
            for (int ks = 0; ks < 4; ks++) ldsm4(qf[ks], qa + ks * 32);
        }

        unsigned stg = sb + Q_TILE + (kb & 1) * KV_STAGE;
        int k0 = kb * AKB;
        if (k0 <= q0 + 16 * w + 15) {     // warp has unmasked rows in this block
            // ---- S = Qh * Kh^T ----
            float s[8][4];
#pragma unroll
            for (int ni = 0; ni < 8; ni++)
#pragma unroll
                for (int e = 0; e < 4; e++) s[ni][e] = 0.0f;
            unsigned kbse = stg + (lane & 7) * KST + (((lane >> 3) & 1) << 4);
#pragma unroll
            for (int ks = 0; ks < 4; ks++)
#pragma unroll
                for (int ni = 0; ni < 8; ni++) {
                    unsigned bf[2];
                    ldsm2(bf, kbse + ni * (8 * KST) + ks * 32);
                    mma_bf16(s[ni], qf[ks], bf);
                }
            // ---- scale + causal mask ----
#pragma unroll
            for (int ni = 0; ni < 8; ni++)
#pragma unroll
                for (int e = 0; e < 4; e++) s[ni][e] *= 0.125f;
            if (k0 + 63 > qr0) {
#pragma unroll
                for (int ni = 0; ni < 8; ni++) {
                    int kc = k0 + ni * 8 + t * 2;
                    if (kc     > qr0)     s[ni][0] = -1e30f;
                    if (kc + 1 > qr0)     s[ni][1] = -1e30f;
                    if (kc     > qr0 + 8) s[ni][2] = -1e30f;
                    if (kc + 1 > qr0 + 8) s[ni][3] = -1e30f;
                }
            }
            // ---- online softmax (warp-local, rows g and g+8) ----
            float bm0 = -1e30f, bm1 = -1e30f;
#pragma unroll
            for (int ni = 0; ni < 8; ni++) {
                bm0 = fmaxf(bm0, fmaxf(s[ni][0], s[ni][1]));
                bm1 = fmaxf(bm1, fmaxf(s[ni][2], s[ni][3]));
            }
            bm0 = fmaxf(bm0, __shfl_xor_sync(0xffffffffu, bm0, 1));
            bm0 = fmaxf(bm0, __shfl_xor_sync(0xffffffffu, bm0, 2));
            bm1 = fmaxf(bm1, __shfl_xor_sync(0xffffffffu, bm1, 1));
            bm1 = fmaxf(bm1, __shfl_xor_sync(0xffffffffu, bm1, 2));
            float mn0 = fmaxf(m0, bm0), mn1 = fmaxf(m1, bm1);
            float a0 = __expf(m0 - mn0), a1 = __expf(m1 - mn1);
            m0 = mn0; m1 = mn1;
            float bs0 = 0.0f, bs1 = 0.0f;
#pragma unroll
            for (int ni = 0; ni < 8; ni++) {
                float p0 = __expf(s[ni][0] - m0), p1 = __expf(s[ni][1] - m0);
                float p2 = __expf(s[ni][2] - m1), p3 = __expf(s[ni][3] - m1);
                bs0 += p0 + p1; bs1 += p2 + p3;
                s[ni][0] = p0; s[ni][1] = p1; s[ni][2] = p2; s[ni][3] = p3;
            }
            bs0 += __shfl_xor_sync(0xffffffffu, bs0, 1);
            bs0 += __shfl_xor_sync(0xffffffffu, bs0, 2);
            bs1 += __shfl_xor_sync(0xffffffffu, bs1, 1);
            bs1 += __shfl_xor_sync(0xffffffffu, bs1, 2);
            l0 = l0 * a0 + bs0;
            l1 = l1 * a1 + bs1;
#pragma unroll
            for (int ni = 0; ni < 8; ni++) {
                o[ni][0] *= a0; o[ni][1] *= a0;
                o[ni][2] *= a1; o[ni][3] *= a1;
            }
            // ---- pack P hi/lo (mma-C layout == mma-A layout) ----
            unsigned ph[8][2], pl[8][2];
#pragma unroll
            for (int ni = 0; ni < 8; ni++) {
#pragma unroll
                for (int rr = 0; rr < 2; rr++) {
                    float vx = s[ni][rr*2], vy = s[ni][rr*2+1];
                    __nv_bfloat16 hx = __float2bfloat16(vx);
                    __nv_bfloat16 hy = __float2bfloat16(vy);
                    __nv_bfloat162 hp = __halves2bfloat162(hx, hy);
                    ph[ni][rr] = *(unsigned*)&hp;
                    pl[ni][rr] = pkbf(vx - __bfloat162float(hx), vy - __bfloat162float(hy));
                }
            }
            // ---- O += P * V (3 split terms), V via ldmatrix.trans ----
            unsigned vbse = stg + KV_TILE + (lane & 15) * KST;
#pragma unroll
            for (int ks = 0; ks < 4; ks++) {
                unsigned aH[4] = { ph[2*ks][0], ph[2*ks][1], ph[2*ks+1][0], ph[2*ks+1][1] };
                unsigned aL[4] = { pl[2*ks][0], pl[2*ks][1], pl[2*ks+1][0], pl[2*ks+1][1] };
#pragma unroll
                for (int ni = 0; ni < 8; ni++) {
                    unsigned bh[2], bl[2];
                    ldsm2t(bh, vbse + ks * (16 * KST) + ni * 16);
                    ldsm2t(bl, vbse + KV_TILE + ks * (16 * KST) + ni * 16);
                    mma_bf16(o[ni], aH, bh);
                    mma_bf16(o[ni], aL, bh);
                    mma_bf16(o[ni], aH, bl);
                }
            }
        }
        __syncthreads();
    }

    // ---- finalize: O/l, write bf16 hi/lo concat layout [b,p,h,d] ----
    float inv0 = 1.0f / l0, inv1 = 1.0f / l1;
    size_t r0off = (size_t)(b * POS + qr0) * DM + h * DH;
    size_t r1off = r0off + (size_t)8 * DM;
#pragma unroll
    for (int ni = 0; ni < 8; ni++) {
        int col = ni * 8 + t * 2;
        float vx = o[ni][0] * inv0, vy = o[ni][1] * inv0;
        __nv_bfloat16 hx = __float2bfloat16(vx), hy = __float2bfloat16(vy);
        *(__nv_bfloat162*)(g_Ah + r0off + col) = __halves2bfloat162(hx, hy);
        *(__nv_bfloat162*)(g_Al + r0off + col) = __halves2bfloat162(
            __float2bfloat16(vx - __bfloat162float(hx)),
            __float2bfloat16(vy - __bfloat162float(hy)));
        float wx = o[ni][2] * inv1, wy = o[ni][3] * inv1;
        __nv_bfloat16 gx = __float2bfloat16(wx), gy = __float2bfloat16(wy);
        *(__nv_bfloat162*)(g_Ah + r1off + col) = __halves2bfloat162(gx, gy);
        *(__nv_bfloat162*)(g_Al + r1off + col) = __halves2bfloat162(
            __float2bfloat16(wx - __bfloat162float(gx)),
            __float2bfloat16(wy - __bfloat162float(gy)));
    }
}

// ---------------- launch ----------------
extern "C" void kernel_launch(void* const* d_in, const int* in_sizes, int n_in,
                              void* d_out, int out_size)
{
    (void)in_sizes; (void)n_in; (void)out_size;
    const float* X  = (const float*)d_in[0];
    const float* Wq = (const float*)d_in[1];
    const float* Wk = (const float*)d_in[2];
    const float* Wv = (const float*)d_in[3];
    const float* Wo = (const float*)d_in[4];
    float* out = (float*)d_out;

    __nv_bfloat16 *Xh, *Xl, *Qh, *Ql, *Kh, *Kl, *Vh, *Vl, *Aah, *Aal;
    __nv_bfloat16 *Wqh, *Wql, *Wkh, *Wkl, *Wvh, *Wvl, *Woh, *Wol;
    cudaGetSymbolAddress((void**)&Xh,  g_Xh);  cudaGetSymbolAddress((void**)&Xl,  g_Xl);
    cudaGetSymbolAddress((void**)&Qh,  g_Qh);  cudaGetSymbolAddress((void**)&Ql,  g_Ql);
    cudaGetSymbolAddress((void**)&Kh,  g_Kh);  cudaGetSymbolAddress((void**)&Kl,  g_Kl);
    cudaGetSymbolAddress((void**)&Vh,  g_Vh);  cudaGetSymbolAddress((void**)&Vl,  g_Vl);
    cudaGetSymbolAddress((void**)&Aah, g_Ah);  cudaGetSymbolAddress((void**)&Aal, g_Al);
    cudaGetSymbolAddress((void**)&Wqh, g_Wqh); cudaGetSymbolAddress((void**)&Wql, g_Wql);
    cudaGetSymbolAddress((void**)&Wkh, g_Wkh); cudaGetSymbolAddress((void**)&Wkl, g_Wkl);
    cudaGetSymbolAddress((void**)&Wvh, g_Wvh); cudaGetSymbolAddress((void**)&Wvl, g_Wvl);
    cudaGetSymbolAddress((void**)&Woh, g_Woh); cudaGetSymbolAddress((void**)&Wol, g_Wol);

    cudaFuncSetAttribute(mma_gemm<0>, cudaFuncAttributeMaxDynamicSharedMemorySize, GEMM_SMEM_BYTES);
    cudaFuncSetAttribute(mma_gemm<1>, cudaFuncAttributeMaxDynamicSharedMemorySize, GEMM_SMEM_BYTES);
    cudaFuncSetAttribute(attn_mma,    cudaFuncAttributeMaxDynamicSharedMemorySize, ATTN_SMEM);

    // 0) precision splits of inputs
    int n4 = TOK * DM / 4;
    split_f32<<<(n4 + 255) / 256, 256>>>((const float4*)X, (__nv_bfloat162*)Xh, (__nv_bfloat162*)Xl, n4);
    int nw = DM * DM;
    split_w<1><<<nw / 256, 256>>>(Wq, Wqh, Wql);
    split_w<1><<<nw / 256, 256>>>(Wk, Wkh, Wkl);
    split_w<1><<<nw / 256, 256>>>(Wv, Wvh, Wvl);
    split_w<0><<<nw / 256, 256>>>(Wo, Woh, Wol);

    // 1) fused QKV projection -> bf16 hi/lo Q,K,V directly
    dim3 g1(DM / 128, TOK / 128, 3);
    mma_gemm<0><<<g1, 256, GEMM_SMEM_BYTES>>>(Xh, Xl, Wqh, Wql, Wkh, Wkl, Wvh, Wvl,
                                              nullptr, Qh, Ql, Kh, Kl, Vh, Vl);

    // 2) causal flash attention on tensor cores -> bf16 hi/lo A directly
    dim3 g2(POS / AQ, HEADS, BATCH);
    attn_mma<<<g2, 256, ATTN_SMEM>>>();

    // 3) out projection -> fp32 output
    dim3 g3(DM / 128, TOK / 128, 1);
    mma_gemm<1><<<g3, 256, GEMM_SMEM_BYTES>>>(Aah, Aal, Woh, Wol, nullptr, nullptr, nullptr, nullptr,
                                              out, nullptr, nullptr, nullptr, nullptr, nullptr, nullptr);
}

// round 10
// speedup vs baseline: 3.1446x; 1.1069x over previous
#include <cuda_runtime.h>
#include <cuda_bf16.h>

#define DM   1024
#define HEADS 16
#define DH    64
#define POS  2048
#define BATCH 2
#define TOK  (BATCH*POS)   // 4096

// ---------------- scratch (device globals: allocation-free) ----------------
__device__ __nv_bfloat16 g_Xh[TOK*DM], g_Xl[TOK*DM];
__device__ __nv_bfloat16 g_Qh[TOK*DM], g_Ql[TOK*DM];
__device__ __nv_bfloat16 g_Kh[TOK*DM], g_Kl[TOK*DM];
__device__ __nv_bfloat16 g_Vh[TOK*DM], g_Vl[TOK*DM];
__device__ __nv_bfloat16 g_Ah[TOK*DM], g_Al[TOK*DM];
__device__ __nv_bfloat16 g_Wqh[DM*DM], g_Wql[DM*DM];
__device__ __nv_bfloat16 g_Wkh[DM*DM], g_Wkl[DM*DM];
__device__ __nv_bfloat16 g_Wvh[DM*DM], g_Wvl[DM*DM];
__device__ __nv_bfloat16 g_Woh[DM*DM], g_Wol[DM*DM];

// ---------------- helpers ----------------
__device__ __forceinline__ unsigned smem_u32(const void* p) {
    unsigned r;
    asm("{ .reg .u64 t; cvta.to.shared.u64 t, %1; cvt.u32.u64 %0, t; }" : "=r"(r) : "l"(p));
    return r;
}
__device__ __forceinline__ void cp16(unsigned s, const void* g) {
    asm volatile("cp.async.cg.shared.global [%0], [%1], 16;" :: "r"(s), "l"(g) : "memory");
}
#define CP_ASYNC_COMMIT() asm volatile("cp.async.commit_group;" ::: "memory")
#define CP_ASYNC_WAIT1()  asm volatile("cp.async.wait_group 1;" ::: "memory")
#define CP_ASYNC_WAIT0()  asm volatile("cp.async.wait_group 0;" ::: "memory")

__device__ __forceinline__ void ldsm4(unsigned* r, unsigned a) {
    asm volatile("ldmatrix.sync.aligned.m8n8.x4.shared.b16 {%0,%1,%2,%3}, [%4];"
        : "=r"(r[0]), "=r"(r[1]), "=r"(r[2]), "=r"(r[3]) : "r"(a));
}
__device__ __forceinline__ void ldsm2(unsigned* r, unsigned a) {
    asm volatile("ldmatrix.sync.aligned.m8n8.x2.shared.b16 {%0,%1}, [%2];"
        : "=r"(r[0]), "=r"(r[1]) : "r"(a));
}
__device__ __forceinline__ void ldsm2t(unsigned* r, unsigned a) {
    asm volatile("ldmatrix.sync.aligned.m8n8.x2.trans.shared.b16 {%0,%1}, [%2];"
        : "=r"(r[0]), "=r"(r[1]) : "r"(a));
}
__device__ __forceinline__ void mma_bf16(float* d, const unsigned* a, const unsigned* b) {
    asm volatile("mma.sync.aligned.m16n8k16.row.col.f32.bf16.bf16.f32 "
        "{%0,%1,%2,%3}, {%4,%5,%6,%7}, {%8,%9}, {%0,%1,%2,%3};"
        : "+f"(d[0]), "+f"(d[1]), "+f"(d[2]), "+f"(d[3])
        : "r"(a[0]), "r"(a[1]), "r"(a[2]), "r"(a[3]), "r"(b[0]), "r"(b[1]));
}
__device__ __forceinline__ unsigned pkbf(float a, float b) {
    __nv_bfloat162 t2 = __halves2bfloat162(__float2bfloat16(a), __float2bfloat16(b));
    return *(unsigned*)&t2;
}

// ---------------- fp32 -> bf16 hi/lo split kernels ----------------
__global__ void split_f32(const float4* __restrict__ src,
                          __nv_bfloat162* __restrict__ h, __nv_bfloat162* __restrict__ l, int n4)
{
    int i = blockIdx.x * blockDim.x + threadIdx.x;
    if (i >= n4) return;
    float4 v = src[i];
    __nv_bfloat16 hx = __float2bfloat16(v.x);
    __nv_bfloat16 hy = __float2bfloat16(v.y);
    __nv_bfloat16 hz = __float2bfloat16(v.z);
    __nv_bfloat16 hw = __float2bfloat16(v.w);
    h[i*2+0] = __halves2bfloat162(hx, hy);
    h[i*2+1] = __halves2bfloat162(hz, hw);
    l[i*2+0] = __halves2bfloat162(__float2bfloat16(v.x - __bfloat162float(hx)),
                                  __float2bfloat16(v.y - __bfloat162float(hy)));
    l[i*2+1] = __halves2bfloat162(__float2bfloat16(v.z - __bfloat162float(hz)),
                                  __float2bfloat16(v.w - __bfloat162float(hw)));
}

// Weight transpose+split via smem tile (coalesced both sides): out[n][k] bf16 hi/lo.
// QKV=1: src (k,n) = W[n>>6][k][n&63].  QKV=0: src (k,n) = W[k*DM+n].
template<int QKV>
__global__ __launch_bounds__(1024)
void split_w(const float* __restrict__ W,
             __nv_bfloat16* __restrict__ h, __nv_bfloat16* __restrict__ l)
{
    __shared__ float tile[32][33];
    int n0 = blockIdx.x * 32, k0 = blockIdx.y * 32;
    int tx = threadIdx.x & 31, ty = threadIdx.x >> 5;
    // read: tx varies n (coalesced; 32-tile never crosses a 64-wide head)
    {
        int n = n0 + tx, k = k0 + ty;
        float x = QKV ? W[(size_t)(n >> 6) * (DM * DH) + (size_t)k * DH + (n & 63)]
                      : W[(size_t)k * DM + n];
        tile[ty][tx] = x;
    }
    __syncthreads();
    // write: tx varies k (coalesced)
    {
        int n = n0 + ty, k = k0 + tx;
        float x = tile[tx][ty];
        __nv_bfloat16 hi = __float2bfloat16(x);
        size_t o = (size_t)n * DM + k;
        h[o] = hi;
        l[o] = __float2bfloat16(x - __bfloat162float(hi));
    }
}

// ---------------- HMMA split-bf16 GEMM: O[4096x1024] = A x B^T ----------------
// MODE 0: epilogue writes bf16 hi/lo (QKV path). MODE 1: fp32 (out-proj).
#define TILE_B   10240
#define STAGE_B  40960
#define NCHUNK   32
#define GEMM_SMEM_BYTES (2*STAGE_B)

template<int MODE>
__global__ __launch_bounds__(256, 2)
void mma_gemm(const __nv_bfloat16* __restrict__ Ah, const __nv_bfloat16* __restrict__ Al,
              const __nv_bfloat16* __restrict__ B0h, const __nv_bfloat16* __restrict__ B0l,
              const __nv_bfloat16* __restrict__ B1h, const __nv_bfloat16* __restrict__ B1l,
              const __nv_bfloat16* __restrict__ B2h, const __nv_bfloat16* __restrict__ B2l,
              float* __restrict__ Of,
              __nv_bfloat16* O0h, __nv_bfloat16* O0l,
              __nv_bfloat16* O1h, __nv_bfloat16* O1l,
              __nv_bfloat16* O2h, __nv_bfloat16* O2l)
{
    extern __shared__ __align__(128) char smem[];
    const unsigned sb = smem_u32(smem);
    int tid = threadIdx.x, lane = tid & 31, wid = tid >> 5;
    int n0 = blockIdx.x * 128, m0 = blockIdx.y * 128;
    int z = blockIdx.z;
    const char* pAh = (const char*)Ah;
    const char* pAl = (const char*)Al;
    const char* pBh = (const char*)((z == 0) ? B0h : (z == 1) ? B1h : B2h);
    const char* pBl = (const char*)((z == 0) ? B0l : (z == 1) ? B1l : B2l);
    __nv_bfloat16* Oh = (z == 0) ? O0h : (z == 1) ? O1h : O2h;
    __nv_bfloat16* Ol = (z == 0) ? O0l : (z == 1) ? O1l : O2l;

    int wm = (wid & 1) * 64;
    int wn = (wid >> 1) * 32;
    int lrow = tid >> 2;
    int lcol = (tid & 3) * 16;

    float acc[4][4][4];
#pragma unroll
    for (int mi = 0; mi < 4; mi++)
#pragma unroll
        for (int ni = 0; ni < 4; ni++)
#pragma unroll
            for (int e = 0; e < 4; e++) acc[mi][ni][e] = 0.0f;

    auto load_chunk = [&](int c, int st) {
        int k0b = c * 64;
#pragma unroll
        for (int half = 0; half < 2; half++) {
            int row = lrow + half * 64;
            unsigned sa = sb + st * STAGE_B + row * 80 + lcol;
            size_t goffA = ((size_t)(m0 + row) * DM) * 2 + k0b + lcol;
            size_t goffB = ((size_t)(n0 + row) * DM) * 2 + k0b + lcol;
            cp16(sa,              pAh + goffA);
            cp16(sa + TILE_B,     pAl + goffA);
            cp16(sa + 2*TILE_B,   pBh + goffB);
            cp16(sa + 3*TILE_B,   pBl + goffB);
        }
    };

    load_chunk(0, 0);
    CP_ASYNC_COMMIT();

    unsigned a_base = (wm + (lane & 15)) * 80 + ((lane >> 4) << 4);
    unsigned b_base = 2*TILE_B + (wn + (lane & 7)) * 80 + (((lane >> 3) & 1) << 4);

    for (int c = 0; c < NCHUNK; c++) {
        if (c + 1 < NCHUNK) {
            load_chunk(c + 1, (c + 1) & 1);
            CP_ASYNC_COMMIT();
            CP_ASYNC_WAIT1();
        } else {
            CP_ASYNC_WAIT0();
        }
        __syncthreads();

        unsigned stb = sb + (c & 1) * STAGE_B;
#pragma unroll
        for (int ks = 0; ks < 2; ks++) {
            unsigned af[4][4], bh[4][2], bl[4][2];
            unsigned ka = stb + ks * 32;
#pragma unroll
            for (int mi = 0; mi < 4; mi++) ldsm4(af[mi], ka + a_base + mi * (16 * 80));
#pragma unroll
            for (int ni = 0; ni < 4; ni++) {
                ldsm2(bh[ni], ka + b_base + ni * (8 * 80));
                ldsm2(bl[ni], ka + b_base + TILE_B + ni * (8 * 80));
            }
#pragma unroll
            for (int mi = 0; mi < 4; mi++)
#pragma unroll
                for (int ni = 0; ni < 4; ni++) mma_bf16(acc[mi][ni], af[mi], bh[ni]);
#pragma unroll
            for (int mi = 0; mi < 4; mi++)
#pragma unroll
                for (int ni = 0; ni < 4; ni++) mma_bf16(acc[mi][ni], af[mi], bl[ni]);
#pragma unroll
            for (int mi = 0; mi < 4; mi++) ldsm4(af[mi], ka + a_base + TILE_B + mi * (16 * 80));
#pragma unroll
            for (int mi = 0; mi < 4; mi++)
#pragma unroll
                for (int ni = 0; ni < 4; ni++) mma_bf16(acc[mi][ni], af[mi], bh[ni]);
        }
        __syncthreads();
    }

    int g = lane >> 2, t = lane & 3;
#pragma unroll
    for (int mi = 0; mi < 4; mi++) {
#pragma unroll
        for (int ni = 0; ni < 4; ni++) {
            int row = m0 + wm + mi * 16 + g;
            int col = n0 + wn + ni * 8 + t * 2;
            if (MODE == 1) {
                float2 v0 = { acc[mi][ni][0], acc[mi][ni][1] };
                float2 v1 = { acc[mi][ni][2], acc[mi][ni][3] };
                *(float2*)(Of + (size_t)row * DM + col)       = v0;
                *(float2*)(Of + (size_t)(row + 8) * DM + col) = v1;
            } else {
#pragma unroll
                for (int rr = 0; rr < 2; rr++) {
                    float vx = acc[mi][ni][rr*2], vy = acc[mi][ni][rr*2+1];
                    __nv_bfloat16 hx = __float2bfloat16(vx);
                    __nv_bfloat16 hy = __float2bfloat16(vy);
                    size_t off = (size_t)(row + rr*8) * DM + col;
                    *(__nv_bfloat162*)(Oh + off) = __halves2bfloat162(hx, hy);
                    *(__nv_bfloat162*)(Ol + off) = __halves2bfloat162(
                        __float2bfloat16(vx - __bfloat162float(hx)),
                        __float2bfloat16(vy - __bfloat162float(hy)));
                }
            }
        }
    }
}

// ---------------- HMMA flash attention (causal) ----------------
// CTA: 128 queries x (b,h). 8 warps, warp = 16 query rows x full 64-key block.
// S = Qh*Kh (1 term).  PV = Ph*Vh + Pl*Vh + Ph*Vl (3 terms).
#define AQ   128
#define AKB  64
#define QST  144
#define KST  144
#define Q_TILE   (AQ*QST)       // 18432
#define KV_TILE  (AKB*KST)      // 9216
#define KV_STAGE (3*KV_TILE)    // 27648
#define ATTN_SMEM (Q_TILE + 2*KV_STAGE)  // 73728

__global__ __launch_bounds__(256, 1)
void attn_mma()
{
    extern __shared__ __align__(128) char smem[];
    const unsigned sb = smem_u32(smem);
    int tid = threadIdx.x, lane = tid & 31, w = tid >> 5;
    int g = lane >> 2, t = lane & 3;
    int qt = (int)gridDim.x - 1 - (int)blockIdx.x;   // big tiles first
    int h = blockIdx.y, b = blockIdx.z;
    int q0 = qt * AQ;
    const char* pQh = (const char*)g_Qh;
    const char* pKh = (const char*)g_Kh;
    const char* pVh = (const char*)g_Vh;
    const char* pVl = (const char*)g_Vl;

    // stage Q tile (128 rows x 128B)
#pragma unroll
    for (int i = 0; i < 4; i++) {
        int idx = tid + 256 * i;          // 0..1023
        int row = idx >> 3, c16 = idx & 7;
        size_t off = ((size_t)(b * POS + q0 + row) * DM + h * DH) * 2 + c16 * 16;
        cp16(sb + row * QST + c16 * 16, pQh + off);
    }

    auto load_kv = [&](int kb, int st) {
        int k0 = kb * AKB;
        unsigned base = sb + Q_TILE + st * KV_STAGE;
#pragma unroll
        for (int i = 0; i < 2; i++) {
            int idx = tid + 256 * i;      // 0..511
            int row = idx >> 3, c16 = idx & 7;
            size_t off = ((size_t)(b * POS + k0 + row) * DM + h * DH) * 2 + c16 * 16;
            unsigned d = base + row * KST + c16 * 16;
            cp16(d,               pKh + off);
            cp16(d + KV_TILE,     pVh + off);
            cp16(d + 2*KV_TILE,   pVl + off);
        }
    };

    load_kv(0, 0);
    CP_ASYNC_COMMIT();

    int nkb = 2 * (qt + 1);
    int qr0 = q0 + 16 * w + g;            // this thread's first query row
    float m0 = -1e30f, m1 = -1e30f, l0 = 0.0f, l1 = 0.0f;
    float o[8][4];
#pragma unroll
    for (int ni = 0; ni < 8; ni++)
#pragma unroll
        for (int e = 0; e < 4; e++) o[ni][e] = 0.0f;

    unsigned qf[4][4];
    unsigned qa = sb + (16 * w + (lane & 15)) * QST + ((lane >> 4) << 4);

    for (int kb = 0; kb < nkb; kb++) {
        if (kb + 1 < nkb) {
            load_kv(kb + 1, (kb + 1) & 1);
            CP_ASYNC_COMMIT();
            CP_ASYNC_WAIT1();
        } else {
            CP_ASYNC_WAIT0();
        }
        __syncthreads();
        if (kb == 0) {                    // Q is resident after first wait
#pragma unroll
            for (int ks = 0; ks < 4; ks++) ldsm4(qf[ks], qa + ks * 32);
        }

        unsigned stg = sb + Q_TILE + (kb & 1) * KV_STAGE;
        int k0 = kb * AKB;
        if (k0 <= q0 + 16 * w + 15) {     // warp has unmasked rows in this block
            // ---- S = Qh * Kh^T ----
            float s[8][4];
#pragma unroll
            for (int ni = 0; ni < 8; ni++)
#pragma unroll
                for (int e = 0; e < 4; e++) s[ni][e] = 0.0f;
            unsigned kbse = stg + (lane & 7) * KST + (((lane >> 3) & 1) << 4);
#pragma unroll
            for (int ks = 0; ks < 4; ks++)
#pragma unroll
                for (int ni = 0; ni < 8; ni++) {
                    unsigned bf[2];
                    ldsm2(bf, kbse + ni * (8 * KST) + ks * 32);
                    mma_bf16(s[ni], qf[ks], bf);
                }
            // ---- scale + causal mask ----
#pragma unroll
            for (int ni = 0; ni < 8; ni++)
#pragma unroll
                for (int e = 0; e < 4; e++) s[ni][e] *= 0.125f;
            if (k0 + 63 > qr0) {
#pragma unroll
                for (int ni = 0; ni < 8; ni++) {
                    int kc = k0 + ni * 8 + t * 2;
                    if (kc     > qr0)     s[ni][0] = -1e30f;
                    if (kc + 1 > qr0)     s[ni][1] = -1e30f;
                    if (kc     > qr0 + 8) s[ni][2] = -1e30f;
                    if (kc + 1 > qr0 + 8) s[ni][3] = -1e30f;
                }
            }
            // ---- online softmax (warp-local, rows g and g+8) ----
            float bm0 = -1e30f, bm1 = -1e30f;
#pragma unroll
            for (int ni = 0; ni < 8; ni++) {
                bm0 = fmaxf(bm0, fmaxf(s[ni][0], s[ni][1]));
                bm1 = fmaxf(bm1, fmaxf(s[ni][2], s[ni][3]));
            }
            bm0 = fmaxf(bm0, __shfl_xor_sync(0xffffffffu, bm0, 1));
            bm0 = fmaxf(bm0, __shfl_xor_sync(0xffffffffu, bm0, 2));
            bm1 = fmaxf(bm1, __shfl_xor_sync(0xffffffffu, bm1, 1));
            bm1 = fmaxf(bm1, __shfl_xor_sync(0xffffffffu, bm1, 2));
            float mn0 = fmaxf(m0, bm0), mn1 = fmaxf(m1, bm1);
            float a0 = __expf(m0 - mn0), a1 = __expf(m1 - mn1);
            m0 = mn0; m1 = mn1;
            float bs0 = 0.0f, bs1 = 0.0f;
#pragma unroll
            for (int ni = 0; ni < 8; ni++) {
                float p0 = __expf(s[ni][0] - m0), p1 = __expf(s[ni][1] - m0);
                float p2 = __expf(s[ni][2] - m1), p3 = __expf(s[ni][3] - m1);
                bs0 += p0 + p1; bs1 += p2 + p3;
                s[ni][0] = p0; s[ni][1] = p1; s[ni][2] = p2; s[ni][3] = p3;
            }
            bs0 += __shfl_xor_sync(0xffffffffu, bs0, 1);
            bs0 += __shfl_xor_sync(0xffffffffu, bs0, 2);
            bs1 += __shfl_xor_sync(0xffffffffu, bs1, 1);
            bs1 += __shfl_xor_sync(0xffffffffu, bs1, 2);
            l0 = l0 * a0 + bs0;
            l1 = l1 * a1 + bs1;
#pragma unroll
            for (int ni = 0; ni < 8; ni++) {
                o[ni][0] *= a0; o[ni][1] *= a0;
                o[ni][2] *= a1; o[ni][3] *= a1;
            }
            // ---- pack P hi/lo (mma-C layout == mma-A layout) ----
            unsigned ph[8][2], pl[8][2];
#pragma unroll
            for (int ni = 0; ni < 8; ni++) {
#pragma unroll
                for (int rr = 0; rr < 2; rr++) {
                    float vx = s[ni][rr*2], vy = s[ni][rr*2+1];
                    __nv_bfloat16 hx = __float2bfloat16(vx);
                    __nv_bfloat16 hy = __float2bfloat16(vy);
                    __nv_bfloat162 hp = __halves2bfloat162(hx, hy);
                    ph[ni][rr] = *(unsigned*)&hp;
                    pl[ni][rr] = pkbf(vx - __bfloat162float(hx), vy - __bfloat162float(hy));
                }
            }
            // ---- O += P * V (3 split terms), V via ldmatrix.trans ----
            unsigned vbse = stg + KV_TILE + (lane & 15) * KST;
#pragma unroll
            for (int ks = 0; ks < 4; ks++) {
                unsigned aH[4] = { ph[2*ks][0], ph[2*ks][1], ph[2*ks+1][0], ph[2*ks+1][1] };
                unsigned aL[4] = { pl[2*ks][0], pl[2*ks][1], pl[2*ks+1][0], pl[2*ks+1][1] };
#pragma unroll
                for (int ni = 0; ni < 8; ni++) {
                    unsigned bh[2], bl[2];
                    ldsm2t(bh, vbse + ks * (16 * KST) + ni * 16);
                    ldsm2t(bl, vbse + KV_TILE + ks * (16 * KST) + ni * 16);
                    mma_bf16(o[ni], aH, bh);
                    mma_bf16(o[ni], aL, bh);
                    mma_bf16(o[ni], aH, bl);
                }
            }
        }
        __syncthreads();
    }

    // ---- finalize: O/l, write bf16 hi/lo concat layout [b,p,h,d] ----
    float inv0 = 1.0f / l0, inv1 = 1.0f / l1;
    size_t r0off = (size_t)(b * POS + qr0) * DM + h * DH;
    size_t r1off = r0off + (size_t)8 * DM;
#pragma unroll
    for (int ni = 0; ni < 8; ni++) {
        int col = ni * 8 + t * 2;
        float vx = o[ni][0] * inv0, vy = o[ni][1] * inv0;
        __nv_bfloat16 hx = __float2bfloat16(vx), hy = __float2bfloat16(vy);
        *(__nv_bfloat162*)(g_Ah + r0off + col) = __halves2bfloat162(hx, hy);
        *(__nv_bfloat162*)(g_Al + r0off + col) = __halves2bfloat162(
            __float2bfloat16(vx - __bfloat162float(hx)),
            __float2bfloat16(vy - __bfloat162float(hy)));
        float wx = o[ni][2] * inv1, wy = o[ni][3] * inv1;
        __nv_bfloat16 gx = __float2bfloat16(wx), gy = __float2bfloat16(wy);
        *(__nv_bfloat162*)(g_Ah + r1off + col) = __halves2bfloat162(gx, gy);
        *(__nv_bfloat162*)(g_Al + r1off + col) = __halves2bfloat162(
            __float2bfloat16(wx - __bfloat162float(gx)),
            __float2bfloat16(wy - __bfloat162float(gy)));
    }
}

// ---------------- launch ----------------
extern "C" void kernel_launch(void* const* d_in, const int* in_sizes, int n_in,
                              void* d_out, int out_size)
{
    (void)in_sizes; (void)n_in; (void)out_size;
    const float* X  = (const float*)d_in[0];
    const float* Wq = (const float*)d_in[1];
    const float* Wk = (const float*)d_in[2];
    const float* Wv = (const float*)d_in[3];
    const float* Wo = (const float*)d_in[4];
    float* out = (float*)d_out;

    __nv_bfloat16 *Xh, *Xl, *Qh, *Ql, *Kh, *Kl, *Vh, *Vl, *Aah, *Aal;
    __nv_bfloat16 *Wqh, *Wql, *Wkh, *Wkl, *Wvh, *Wvl, *Woh, *Wol;
    cudaGetSymbolAddress((void**)&Xh,  g_Xh);  cudaGetSymbolAddress((void**)&Xl,  g_Xl);
    cudaGetSymbolAddress((void**)&Qh,  g_Qh);  cudaGetSymbolAddress((void**)&Ql,  g_Ql);
    cudaGetSymbolAddress((void**)&Kh,  g_Kh);  cudaGetSymbolAddress((void**)&Kl,  g_Kl);
    cudaGetSymbolAddress((void**)&Vh,  g_Vh);  cudaGetSymbolAddress((void**)&Vl,  g_Vl);
    cudaGetSymbolAddress((void**)&Aah, g_Ah);  cudaGetSymbolAddress((void**)&Aal, g_Al);
    cudaGetSymbolAddress((void**)&Wqh, g_Wqh); cudaGetSymbolAddress((void**)&Wql, g_Wql);
    cudaGetSymbolAddress((void**)&Wkh, g_Wkh); cudaGetSymbolAddress((void**)&Wkl, g_Wkl);
    cudaGetSymbolAddress((void**)&Wvh, g_Wvh); cudaGetSymbolAddress((void**)&Wvl, g_Wvl);
    cudaGetSymbolAddress((void**)&Woh, g_Woh); cudaGetSymbolAddress((void**)&Wol, g_Wol);

    cudaFuncSetAttribute(mma_gemm<0>, cudaFuncAttributeMaxDynamicSharedMemorySize, GEMM_SMEM_BYTES);
    cudaFuncSetAttribute(mma_gemm<1>, cudaFuncAttributeMaxDynamicSharedMemorySize, GEMM_SMEM_BYTES);
    cudaFuncSetAttribute(attn_mma,    cudaFuncAttributeMaxDynamicSharedMemorySize, ATTN_SMEM);

    // 0) precision splits of inputs
    int n4 = TOK * DM / 4;
    split_f32<<<(n4 + 255) / 256, 256>>>((const float4*)X, (__nv_bfloat162*)Xh, (__nv_bfloat162*)Xl, n4);
    dim3 gw(DM / 32, DM / 32);
    split_w<1><<<gw, 1024>>>(Wq, Wqh, Wql);
    split_w<1><<<gw, 1024>>>(Wk, Wkh, Wkl);
    split_w<1><<<gw, 1024>>>(Wv, Wvh, Wvl);
    split_w<0><<<gw, 1024>>>(Wo, Woh, Wol);

    // 1) fused QKV projection -> bf16 hi/lo Q,K,V directly
    dim3 g1(DM / 128, TOK / 128, 3);
    mma_gemm<0><<<g1, 256, GEMM_SMEM_BYTES>>>(Xh, Xl, Wqh, Wql, Wkh, Wkl, Wvh, Wvl,
                                              nullptr, Qh, Ql, Kh, Kl, Vh, Vl);

    // 2) causal flash attention on tensor cores -> bf16 hi/lo A directly
    dim3 g2(POS / AQ, HEADS, BATCH);
    attn_mma<<<g2, 256, ATTN_SMEM>>>();

    // 3) out projection -> fp32 output
    dim3 g3(DM / 128, TOK / 128, 1);
    mma_gemm<1><<<g3, 256, GEMM_SMEM_BYTES>>>(Aah, Aal, Woh, Wol, nullptr, nullptr, nullptr, nullptr,
                                              out, nullptr, nullptr, nullptr, nullptr, nullptr, nullptr);
}